// round 1
// baseline (speedup 1.0000x reference)
#include <cuda_runtime.h>

#define B_  2
#define S_  2048
#define D_  1024
#define H_  16
#define HD_ 64
#define SCALE_ 0.125f   // HD^-0.5 = 1/8

// Scratch (allocation-free rule: device globals)
__device__ float g_Q[B_*H_*S_*HD_];     // 16 MB
__device__ float g_K[B_*H_*S_*HD_];     // 16 MB
__device__ float g_V[B_*H_*S_*HD_];     // 16 MB
__device__ float g_att[B_*S_*D_];       // 32 MB  [B*S, D] row-major, col = h*64+hd

// ---------------------------------------------------------------------------
// QKV GEMM: [4096,1024] x [1024,3072] + bias -> scatter into Q/K/V [B,H,S,HD]
// 128x128 tile, BK=8, 256 threads, 8x8 micro-tile.
// ---------------------------------------------------------------------------
__global__ __launch_bounds__(256) void qkv_gemm(const float* __restrict__ A,
                                                const float* __restrict__ Bw,
                                                const float* __restrict__ bias) {
    const int K = D_, N = 3 * D_;
    __shared__ float As[8][128];
    __shared__ float Bs[8][128];

    const int tid = threadIdx.x;
    const int tx = tid & 15, ty = tid >> 4;
    const int rowBase = blockIdx.y * 128;
    const int colBase = blockIdx.x * 128;

    const int lr = tid >> 1;          // A-load row 0..127
    const int lk = (tid & 1) * 4;     // A-load k offset 0/4
    const int bkr = tid >> 5;         // B-load k row 0..7
    const int bc  = (tid & 31) * 4;   // B-load col offset

    const float* Aptr = A  + (size_t)(rowBase + lr) * K + lk;
    const float* Bptr = Bw + (size_t)bkr * N + colBase + bc;

    float c[8][8];
    #pragma unroll
    for (int i = 0; i < 8; i++)
        #pragma unroll
        for (int j = 0; j < 8; j++) c[i][j] = 0.f;

    for (int k0 = 0; k0 < K; k0 += 8) {
        float4 av = *(const float4*)(Aptr + k0);
        float4 bv = *(const float4*)(Bptr + (size_t)k0 * N);
        __syncthreads();
        As[lk + 0][lr] = av.x; As[lk + 1][lr] = av.y;
        As[lk + 2][lr] = av.z; As[lk + 3][lr] = av.w;
        *(float4*)(&Bs[bkr][bc]) = bv;
        __syncthreads();
        #pragma unroll
        for (int kk = 0; kk < 8; kk++) {
            float ra[8], rb[8];
            *(float4*)(ra)     = *(const float4*)(&As[kk][ty * 8]);
            *(float4*)(ra + 4) = *(const float4*)(&As[kk][ty * 8 + 4]);
            *(float4*)(rb)     = *(const float4*)(&Bs[kk][tx * 8]);
            *(float4*)(rb + 4) = *(const float4*)(&Bs[kk][tx * 8 + 4]);
            #pragma unroll
            for (int i = 0; i < 8; i++)
                #pragma unroll
                for (int j = 0; j < 8; j++)
                    c[i][j] += ra[i] * rb[j];
        }
    }

    // Epilogue: bias + scatter to Q/K/V in [B,H,S,HD]
    #pragma unroll
    for (int i = 0; i < 8; i++) {
        const int m = rowBase + ty * 8 + i;
        const int b = m >> 11;        // /2048
        const int s = m & 2047;
        #pragma unroll
        for (int j = 0; j < 8; j++) {
            const int n = colBase + tx * 8 + j;
            const float v = c[i][j] + bias[n];
            const int which = n >> 10;
            const int d = n & 1023;
            const int h = d >> 6;
            const int hd = d & 63;
            float* dst = (which == 0) ? g_Q : (which == 1) ? g_K : g_V;
            dst[(((size_t)(b * H_ + h)) * S_ + s) * HD_ + hd] = v;
        }
    }
}

// ---------------------------------------------------------------------------
// Flash attention: one CTA per (b, h, 64-row q tile). 128 threads.
// Online softmax over 32-key tiles. K tile smem reused for P (stride 33).
// ---------------------------------------------------------------------------
__global__ __launch_bounds__(128) void attn_kernel() {
    const int qt = blockIdx.x;   // 0..31
    const int h  = blockIdx.y;
    const int b  = blockIdx.z;

    const float* Qg = g_Q + ((size_t)(b * H_ + h) * S_ + qt * 64) * HD_;
    const float* Kg = g_K + (size_t)(b * H_ + h) * S_ * HD_;
    const float* Vg = g_V + (size_t)(b * H_ + h) * S_ * HD_;

    __shared__ float Qs[64][68];
    __shared__ float KP_raw[32 * 68];   // K tile (stride 68) aliased as P (stride 33)
    __shared__ float Vs_raw[32 * 68];
    __shared__ float m_s[64], l_s[64], al_s[64];

    #define Kmat(r, c_) KP_raw[(r) * 68 + (c_)]
    #define Pmat(i, j_) KP_raw[(i) * 33 + (j_)]
    #define Vmat(r, c_) Vs_raw[(r) * 68 + (c_)]

    const int tid = threadIdx.x;

    // load Q tile (64x64)
    for (int i = tid; i < 64 * 16; i += 128) {
        const int r = i >> 4, c4 = (i & 15) * 4;
        *(float4*)&Qs[r][c4] = *(const float4*)(Qg + r * 64 + c4);
    }
    if (tid < 64) { m_s[tid] = -1e30f; l_s[tid] = 0.f; }

    // thread mappings
    const int ig = tid >> 3;          // score rows 4*ig .. +3
    const int jg = tid & 7;           // score cols jg + 8*jj
    const int si = tid >> 1, sh = tid & 1;       // softmax: row, half
    const int pr = (tid >> 2) * 2;    // PV rows pr, pr+1
    const int pd = (tid & 3) * 16;    // PV dims pd .. +15

    float o[2][16];
    #pragma unroll
    for (int r = 0; r < 2; r++)
        #pragma unroll
        for (int d = 0; d < 16; d++) o[r][d] = 0.f;

    for (int kt = 0; kt < S_ / 32; kt++) {
        __syncthreads();   // prev PV done; Q visible on first iter
        for (int i = tid; i < 32 * 16; i += 128) {
            const int r = i >> 4, c4 = (i & 15) * 4;
            *(float4*)&Kmat(r, c4) = *(const float4*)(Kg + (size_t)(kt * 32 + r) * 64 + c4);
            *(float4*)&Vmat(r, c4) = *(const float4*)(Vg + (size_t)(kt * 32 + r) * 64 + c4);
        }
        __syncthreads();

        // scores: 4 rows x 4 cols per thread
        float acc[4][4];
        #pragma unroll
        for (int i = 0; i < 4; i++)
            #pragma unroll
            for (int j = 0; j < 4; j++) acc[i][j] = 0.f;

        #pragma unroll 8
        for (int d = 0; d < 64; d++) {
            float qv[4], kv[4];
            #pragma unroll
            for (int ii = 0; ii < 4; ii++) qv[ii] = Qs[4 * ig + ii][d];
            #pragma unroll
            for (int jj = 0; jj < 4; jj++) kv[jj] = Kmat(jg + 8 * jj, d);
            #pragma unroll
            for (int ii = 0; ii < 4; ii++)
                #pragma unroll
                for (int jj = 0; jj < 4; jj++)
                    acc[ii][jj] += qv[ii] * kv[jj];
        }
        __syncthreads();   // done reading K tile

        #pragma unroll
        for (int ii = 0; ii < 4; ii++)
            #pragma unroll
            for (int jj = 0; jj < 4; jj++)
                Pmat(4 * ig + ii, jg + 8 * jj) = acc[ii][jj] * SCALE_;
        __syncthreads();

        // online softmax: 2 threads per row, 16 keys each
        {
            float mloc = -1e30f;
            #pragma unroll
            for (int jj = 0; jj < 16; jj++)
                mloc = fmaxf(mloc, Pmat(si, sh * 16 + jj));
            mloc = fmaxf(mloc, __shfl_xor_sync(0xffffffffu, mloc, 1));
            const float mprev = m_s[si];
            const float mnew  = fmaxf(mprev, mloc);
            float lsum = 0.f;
            #pragma unroll
            for (int jj = 0; jj < 16; jj++) {
                const float p = __expf(Pmat(si, sh * 16 + jj) - mnew);
                Pmat(si, sh * 16 + jj) = p;
                lsum += p;
            }
            lsum += __shfl_xor_sync(0xffffffffu, lsum, 1);
            if (sh == 0) {
                const float al = __expf(mprev - mnew);
                al_s[si] = al;
                l_s[si]  = l_s[si] * al + lsum;
                m_s[si]  = mnew;
            }
        }
        __syncthreads();

        // PV accumulate: 2 rows x 16 dims per thread
        {
            const float al0 = al_s[pr], al1 = al_s[pr + 1];
            #pragma unroll
            for (int d = 0; d < 16; d++) { o[0][d] *= al0; o[1][d] *= al1; }
            #pragma unroll 4
            for (int j = 0; j < 32; j++) {
                const float p0 = Pmat(pr, j);
                const float p1 = Pmat(pr + 1, j);
                #pragma unroll
                for (int q = 0; q < 4; q++) {
                    const float4 v4 = *(const float4*)&Vmat(j, pd + 4 * q);
                    o[0][4 * q + 0] += p0 * v4.x; o[1][4 * q + 0] += p1 * v4.x;
                    o[0][4 * q + 1] += p0 * v4.y; o[1][4 * q + 1] += p1 * v4.y;
                    o[0][4 * q + 2] += p0 * v4.z; o[1][4 * q + 2] += p1 * v4.z;
                    o[0][4 * q + 3] += p0 * v4.w; o[1][4 * q + 3] += p1 * v4.w;
                }
            }
        }
    }

    // normalize + write to g_att [B*S, D] (col = h*64 + d)
    #pragma unroll
    for (int rr = 0; rr < 2; rr++) {
        const int row = qt * 64 + pr + rr;
        const float inv = 1.f / l_s[pr + rr];
        float* dst = g_att + ((size_t)(b * S_ + row)) * D_ + h * 64 + pd;
        #pragma unroll
        for (int d = 0; d < 16; d++) dst[d] = o[rr][d] * inv;
    }
    #undef Kmat
    #undef Pmat
    #undef Vmat
}

// ---------------------------------------------------------------------------
// Proj GEMM: g_att [4096,1024] x Wproj [1024,1024] + bias -> out
// ---------------------------------------------------------------------------
__global__ __launch_bounds__(256) void proj_gemm(const float* __restrict__ Bw,
                                                 const float* __restrict__ bias,
                                                 float* __restrict__ out) {
    const int K = D_, N = D_;
    __shared__ float As[8][128];
    __shared__ float Bs[8][128];

    const int tid = threadIdx.x;
    const int tx = tid & 15, ty = tid >> 4;
    const int rowBase = blockIdx.y * 128;
    const int colBase = blockIdx.x * 128;

    const int lr = tid >> 1;
    const int lk = (tid & 1) * 4;
    const int bkr = tid >> 5;
    const int bc  = (tid & 31) * 4;

    const float* Aptr = g_att + (size_t)(rowBase + lr) * K + lk;
    const float* Bptr = Bw + (size_t)bkr * N + colBase + bc;

    float c[8][8];
    #pragma unroll
    for (int i = 0; i < 8; i++)
        #pragma unroll
        for (int j = 0; j < 8; j++) c[i][j] = 0.f;

    for (int k0 = 0; k0 < K; k0 += 8) {
        float4 av = *(const float4*)(Aptr + k0);
        float4 bv = *(const float4*)(Bptr + (size_t)k0 * N);
        __syncthreads();
        As[lk + 0][lr] = av.x; As[lk + 1][lr] = av.y;
        As[lk + 2][lr] = av.z; As[lk + 3][lr] = av.w;
        *(float4*)(&Bs[bkr][bc]) = bv;
        __syncthreads();
        #pragma unroll
        for (int kk = 0; kk < 8; kk++) {
            float ra[8], rb[8];
            *(float4*)(ra)     = *(const float4*)(&As[kk][ty * 8]);
            *(float4*)(ra + 4) = *(const float4*)(&As[kk][ty * 8 + 4]);
            *(float4*)(rb)     = *(const float4*)(&Bs[kk][tx * 8]);
            *(float4*)(rb + 4) = *(const float4*)(&Bs[kk][tx * 8 + 4]);
            #pragma unroll
            for (int i = 0; i < 8; i++)
                #pragma unroll
                for (int j = 0; j < 8; j++)
                    c[i][j] += ra[i] * rb[j];
        }
    }

    #pragma unroll
    for (int i = 0; i < 8; i++) {
        const int m = rowBase + ty * 8 + i;
        #pragma unroll
        for (int j = 0; j < 8; j += 4) {
            const int n = colBase + tx * 8 + j;
            float4 v;
            v.x = c[i][j + 0] + bias[n + 0];
            v.y = c[i][j + 1] + bias[n + 1];
            v.z = c[i][j + 2] + bias[n + 2];
            v.w = c[i][j + 3] + bias[n + 3];
            *(float4*)(out + (size_t)m * N + n) = v;
        }
    }
}

// ---------------------------------------------------------------------------
extern "C" void kernel_launch(void* const* d_in, const int* in_sizes, int n_in,
                              void* d_out, int out_size) {
    const float* x     = (const float*)d_in[0];
    const float* Wqkv  = (const float*)d_in[1];
    const float* bqkv  = (const float*)d_in[2];
    const float* Wproj = (const float*)d_in[3];
    const float* bproj = (const float*)d_in[4];
    float* out = (float*)d_out;

    dim3 g1(3 * D_ / 128, (B_ * S_) / 128);   // 24 x 32
    qkv_gemm<<<g1, 256>>>(x, Wqkv, bqkv);

    dim3 g2(S_ / 64, H_, B_);                 // 32 x 16 x 2
    attn_kernel<<<g2, 128>>>();

    dim3 g3(D_ / 128, (B_ * S_) / 128);       // 8 x 32
    proj_gemm<<<g3, 256>>>(Wproj, bproj, out);
}

// round 3
// speedup vs baseline: 3.6007x; 3.6007x over previous
#include <cuda_runtime.h>
#include <cuda_bf16.h>

#define B_  2
#define S_  2048
#define D_  1024
#define H_  16
#define HD_ 64
#define SCALE_ 0.125f
#define NTOK (B_*S_)   /* 4096 */

// ---------------- device scratch (allocation-free rule) ----------------
__device__ __nv_bfloat16 g_xh[NTOK*D_],  g_xl[NTOK*D_];
__device__ __nv_bfloat16 g_wqh[D_*3*D_], g_wql[D_*3*D_];
__device__ __nv_bfloat16 g_wph[D_*D_],   g_wpl[D_*D_];
__device__ __nv_bfloat16 g_Qh[NTOK*D_],  g_Ql[NTOK*D_];   // [B,H,S,HD], Q pre-scaled
__device__ __nv_bfloat16 g_Kh[NTOK*D_],  g_Kl[NTOK*D_];
__device__ __nv_bfloat16 g_Vh[NTOK*D_],  g_Vl[NTOK*D_];
__device__ __nv_bfloat16 g_ah[NTOK*D_],  g_al[NTOK*D_];   // attention out [4096,1024]

// ---------------- helpers ----------------
__device__ __forceinline__ unsigned smaddr(const void* p) {
    return (unsigned)__cvta_generic_to_shared(p);
}
__device__ __forceinline__ void ldsm4(unsigned r[4], unsigned a) {
    asm volatile("ldmatrix.sync.aligned.m8n8.x4.shared.b16 {%0,%1,%2,%3}, [%4];"
                 : "=r"(r[0]), "=r"(r[1]), "=r"(r[2]), "=r"(r[3]) : "r"(a));
}
__device__ __forceinline__ void ldsm4t(unsigned r[4], unsigned a) {
    asm volatile("ldmatrix.sync.aligned.m8n8.x4.trans.shared.b16 {%0,%1,%2,%3}, [%4];"
                 : "=r"(r[0]), "=r"(r[1]), "=r"(r[2]), "=r"(r[3]) : "r"(a));
}
__device__ __forceinline__ void mma_bf16(float c[4], const unsigned a[4],
                                         unsigned b0, unsigned b1) {
    asm volatile(
        "mma.sync.aligned.m16n8k16.row.col.f32.bf16.bf16.f32 "
        "{%0,%1,%2,%3},{%4,%5,%6,%7},{%8,%9},{%0,%1,%2,%3};"
        : "+f"(c[0]), "+f"(c[1]), "+f"(c[2]), "+f"(c[3])
        : "r"(a[0]), "r"(a[1]), "r"(a[2]), "r"(a[3]), "r"(b0), "r"(b1));
}
// split two fp32 into packed-bf16 hi pair + lo pair
__device__ __forceinline__ void split2(float v0, float v1, unsigned& hp, unsigned& lp) {
    __nv_bfloat16 h0 = __float2bfloat16(v0), h1 = __float2bfloat16(v1);
    float r0 = v0 - __bfloat162float(h0), r1 = v1 - __bfloat162float(h1);
    __nv_bfloat162 hh = __halves2bfloat162(h0, h1);
    __nv_bfloat162 ll = __floats2bfloat162_rn(r0, r1);
    hp = *reinterpret_cast<unsigned*>(&hh);
    lp = *reinterpret_cast<unsigned*>(&ll);
}

// ---------------- split-convert kernels (globals referenced in device code) ----
__device__ __forceinline__ void conv4(float4 v, __nv_bfloat16* h, __nv_bfloat16* l, size_t idx) {
    unsigned h0, l0, h1, l1;
    split2(v.x, v.y, h0, l0);
    split2(v.z, v.w, h1, l1);
    *(unsigned*)(h + idx)     = h0;  *(unsigned*)(h + idx + 2) = h1;
    *(unsigned*)(l + idx)     = l0;  *(unsigned*)(l + idx + 2) = l1;
}
__global__ void conv_x(const float* __restrict__ s) {
    size_t i = (size_t)blockIdx.x * 256 + threadIdx.x;
    conv4(((const float4*)s)[i], g_xh, g_xl, i * 4);
}
__global__ void conv_wqkv(const float* __restrict__ s) {
    size_t i = (size_t)blockIdx.x * 256 + threadIdx.x;
    conv4(((const float4*)s)[i], g_wqh, g_wql, i * 4);
}
__global__ void conv_wproj(const float* __restrict__ s) {
    size_t i = (size_t)blockIdx.x * 256 + threadIdx.x;
    conv4(((const float4*)s)[i], g_wph, g_wpl, i * 4);
}

// ---------------- split-bf16 GEMM (128x128 tile, BK=32, 8 warps) ----------------
// MODE 0: QKV  (A=g_x, B=g_wq; bias, Q*SCALE, scatter split-bf16 to g_Q/K/V)
// MODE 1: proj (A=g_a, B=g_wp; bias, fp32 out)
template <int GN, int MODE>
__global__ __launch_bounds__(256) void gemm_split(const float* __restrict__ bias,
                                                  float* __restrict__ outp) {
    // device-side global selection (NEVER pass __device__ symbols from host!)
    const __nv_bfloat16* __restrict__ Ah = (MODE == 0) ? g_xh : g_ah;
    const __nv_bfloat16* __restrict__ Al = (MODE == 0) ? g_xl : g_al;
    const __nv_bfloat16* __restrict__ Bh = (MODE == 0) ? g_wqh : g_wph;
    const __nv_bfloat16* __restrict__ Bl = (MODE == 0) ? g_wql : g_wpl;

    __shared__ __nv_bfloat16 As0[128 * 40], As1[128 * 40];   // rows padded to 40 bf16
    __shared__ __nv_bfloat16 Bs0[32 * 136], Bs1[32 * 136];   // rows padded to 136 bf16

    const int tid = threadIdx.x, l = tid & 31, wid = tid >> 5;
    const int wm = (wid & 1) * 64, wn = (wid >> 1) * 32;
    const int rowBase = blockIdx.y * 128, colBase = blockIdx.x * 128;

    const int ar = tid >> 2,  ac = (tid & 3) * 8;    // A loads: rows ar, ar+64
    const int br = tid >> 4,  bc = (tid & 15) * 8;   // B loads: rows br, br+16

    const __nv_bfloat16* gA0 = Ah + (size_t)(rowBase + ar) * D_ + ac;
    const __nv_bfloat16* gA1 = Al + (size_t)(rowBase + ar) * D_ + ac;
    const __nv_bfloat16* gB0 = Bh + (size_t)br * GN + colBase + bc;
    const __nv_bfloat16* gB1 = Bl + (size_t)br * GN + colBase + bc;

    float c[4][4][4];
#pragma unroll
    for (int i = 0; i < 4; i++)
#pragma unroll
        for (int j = 0; j < 4; j++)
#pragma unroll
            for (int k = 0; k < 4; k++) c[i][j][k] = 0.f;

    // first tile gmem -> smem
    *(uint4*)&As0[ar * 40 + ac]        = *(const uint4*)(gA0);
    *(uint4*)&As0[(ar + 64) * 40 + ac] = *(const uint4*)(gA0 + (size_t)64 * D_);
    *(uint4*)&As1[ar * 40 + ac]        = *(const uint4*)(gA1);
    *(uint4*)&As1[(ar + 64) * 40 + ac] = *(const uint4*)(gA1 + (size_t)64 * D_);
    *(uint4*)&Bs0[br * 136 + bc]       = *(const uint4*)(gB0);
    *(uint4*)&Bs0[(br + 16) * 136 + bc]= *(const uint4*)(gB0 + (size_t)16 * GN);
    *(uint4*)&Bs1[br * 136 + bc]       = *(const uint4*)(gB1);
    *(uint4*)&Bs1[(br + 16) * 136 + bc]= *(const uint4*)(gB1 + (size_t)16 * GN);
    __syncthreads();

    const int nK = D_ / 32;
    for (int kt = 0; kt < nK; kt++) {
        uint4 pa0a, pa0b, pa1a, pa1b, pb0a, pb0b, pb1a, pb1b;
        if (kt + 1 < nK) {
            const size_t aoff = (size_t)(kt + 1) * 32;
            pa0a = *(const uint4*)(gA0 + aoff);
            pa0b = *(const uint4*)(gA0 + aoff + (size_t)64 * D_);
            pa1a = *(const uint4*)(gA1 + aoff);
            pa1b = *(const uint4*)(gA1 + aoff + (size_t)64 * D_);
            const size_t boff = (size_t)(kt + 1) * 32 * GN;
            pb0a = *(const uint4*)(gB0 + boff);
            pb0b = *(const uint4*)(gB0 + boff + (size_t)16 * GN);
            pb1a = *(const uint4*)(gB1 + boff);
            pb1b = *(const uint4*)(gB1 + boff + (size_t)16 * GN);
        }

#pragma unroll
        for (int k0 = 0; k0 < 32; k0 += 16) {
            unsigned ah[4][4], al[4][4];
            const int arow = wm + (l & 15);
            const int akc  = k0 + ((l >> 4) & 1) * 8;
#pragma unroll
            for (int mi = 0; mi < 4; mi++) {
                ldsm4(ah[mi], smaddr(&As0[(arow + mi * 16) * 40 + akc]));
                ldsm4(al[mi], smaddr(&As1[(arow + mi * 16) * 40 + akc]));
            }
            const int brow = k0 + ((l >> 3) & 1) * 8 + (l & 7);
            const int bcol = wn + (l >> 4) * 8;
#pragma unroll
            for (int nj = 0; nj < 2; nj++) {
                unsigned bh[4], bl[4];
                ldsm4t(bh, smaddr(&Bs0[brow * 136 + bcol + nj * 16]));
                ldsm4t(bl, smaddr(&Bs1[brow * 136 + bcol + nj * 16]));
#pragma unroll
                for (int mi = 0; mi < 4; mi++) {
                    mma_bf16(c[mi][2 * nj],     ah[mi], bh[0], bh[1]);
                    mma_bf16(c[mi][2 * nj],     ah[mi], bl[0], bl[1]);
                    mma_bf16(c[mi][2 * nj],     al[mi], bh[0], bh[1]);
                    mma_bf16(c[mi][2 * nj + 1], ah[mi], bh[2], bh[3]);
                    mma_bf16(c[mi][2 * nj + 1], ah[mi], bl[2], bl[3]);
                    mma_bf16(c[mi][2 * nj + 1], al[mi], bh[2], bh[3]);
                }
            }
        }

        if (kt + 1 < nK) {
            __syncthreads();
            *(uint4*)&As0[ar * 40 + ac]         = pa0a;
            *(uint4*)&As0[(ar + 64) * 40 + ac]  = pa0b;
            *(uint4*)&As1[ar * 40 + ac]         = pa1a;
            *(uint4*)&As1[(ar + 64) * 40 + ac]  = pa1b;
            *(uint4*)&Bs0[br * 136 + bc]        = pb0a;
            *(uint4*)&Bs0[(br + 16) * 136 + bc] = pb0b;
            *(uint4*)&Bs1[br * 136 + bc]        = pb1a;
            *(uint4*)&Bs1[(br + 16) * 136 + bc] = pb1b;
            __syncthreads();
        }
    }

    // epilogue
#pragma unroll
    for (int mi = 0; mi < 4; mi++) {
        const int r0 = rowBase + wm + mi * 16 + (l >> 2);
        const int r1 = r0 + 8;
#pragma unroll
        for (int g = 0; g < 4; g++) {
            const int nn = colBase + wn + g * 8 + 2 * (l & 3);
            if (MODE == 1) {
                float2 w;
                w.x = c[mi][g][0] + bias[nn];
                w.y = c[mi][g][1] + bias[nn + 1];
                *(float2*)(outp + (size_t)r0 * GN + nn) = w;
                w.x = c[mi][g][2] + bias[nn];
                w.y = c[mi][g][3] + bias[nn + 1];
                *(float2*)(outp + (size_t)r1 * GN + nn) = w;
            } else {
                const int which = nn >> 10, d = nn & 1023, hh = d >> 6, hd = d & 63;
                const float sc = (which == 0) ? SCALE_ : 1.f;
                __nv_bfloat16* dh = (which == 0) ? g_Qh : (which == 1) ? g_Kh : g_Vh;
                __nv_bfloat16* dl = (which == 0) ? g_Ql : (which == 1) ? g_Kl : g_Vl;
                const int b0i = r0 >> 11, s0i = r0 & 2047;
                const int b1i = r1 >> 11, s1i = r1 & 2047;
                const size_t i0 = (((size_t)(b0i * H_ + hh)) * S_ + s0i) * HD_ + hd;
                const size_t i1 = (((size_t)(b1i * H_ + hh)) * S_ + s1i) * HD_ + hd;
                unsigned hp, lp;
                split2((c[mi][g][0] + bias[nn]) * sc, (c[mi][g][1] + bias[nn + 1]) * sc, hp, lp);
                *(unsigned*)(dh + i0) = hp; *(unsigned*)(dl + i0) = lp;
                split2((c[mi][g][2] + bias[nn]) * sc, (c[mi][g][3] + bias[nn + 1]) * sc, hp, lp);
                *(unsigned*)(dh + i1) = hp; *(unsigned*)(dl + i1) = lp;
            }
        }
    }
}

// ---------------- flash attention, mma.sync split-bf16 ----------------
// CTA: (qt, h, b); 128 threads = 4 warps; 64 q-rows per CTA, 64-key tiles.
__global__ __launch_bounds__(128) void attn_mma() {
    const int qt = blockIdx.x, h = blockIdx.y, b = blockIdx.z;
    const int tid = threadIdx.x, l = tid & 31, wid = tid >> 5;

    __shared__ __nv_bfloat16 Ks0[64 * 72], Ks1[64 * 72];   // rows padded to 72 bf16
    __shared__ __nv_bfloat16 Vs0[64 * 72], Vs1[64 * 72];

    const size_t headOff = ((size_t)(b * H_ + h)) * S_ * HD_;
    const __nv_bfloat16* Qh_g = g_Qh + headOff + (size_t)qt * 64 * HD_;
    const __nv_bfloat16* Ql_g = g_Ql + headOff + (size_t)qt * 64 * HD_;
    const __nv_bfloat16* Kh_g = g_Kh + headOff;
    const __nv_bfloat16* Kl_g = g_Kl + headOff;
    const __nv_bfloat16* Vh_g = g_Vh + headOff;
    const __nv_bfloat16* Vl_g = g_Vl + headOff;

    // stage Q in K smem, extract fragments to registers
    for (int i = tid; i < 64 * 8; i += 128) {
        const int r = i >> 3, cc = (i & 7) * 8;
        *(uint4*)&Ks0[r * 72 + cc] = *(const uint4*)(Qh_g + (size_t)r * HD_ + cc);
        *(uint4*)&Ks1[r * 72 + cc] = *(const uint4*)(Ql_g + (size_t)r * HD_ + cc);
    }
    __syncthreads();
    unsigned qh[4][4], ql[4][4];
    {
        const int row = wid * 16 + (l & 15);
        const int kc  = ((l >> 4) & 1) * 8;
#pragma unroll
        for (int ks = 0; ks < 4; ks++) {
            ldsm4(qh[ks], smaddr(&Ks0[row * 72 + ks * 16 + kc]));
            ldsm4(ql[ks], smaddr(&Ks1[row * 72 + ks * 16 + kc]));
        }
    }
    __syncthreads();

    float m0 = -1e30f, m1 = -1e30f, l0 = 0.f, l1 = 0.f;
    float o[8][4];
#pragma unroll
    for (int g = 0; g < 8; g++)
#pragma unroll
        for (int k = 0; k < 4; k++) o[g][k] = 0.f;

    for (int kt = 0; kt < S_ / 64; kt++) {
        const size_t koff = (size_t)kt * 64 * HD_;
        for (int i = tid; i < 64 * 8; i += 128) {
            const int r = i >> 3, cc = (i & 7) * 8;
            const size_t src = koff + (size_t)r * HD_ + cc;
            *(uint4*)&Ks0[r * 72 + cc] = *(const uint4*)(Kh_g + src);
            *(uint4*)&Ks1[r * 72 + cc] = *(const uint4*)(Kl_g + src);
            *(uint4*)&Vs0[r * 72 + cc] = *(const uint4*)(Vh_g + src);
            *(uint4*)&Vs1[r * 72 + cc] = *(const uint4*)(Vl_g + src);
        }
        __syncthreads();

        // scores: Q (A frags) x K (B frags, non-trans: K rows are keys, d contiguous)
        float sc[8][4];
#pragma unroll
        for (int g = 0; g < 8; g++)
#pragma unroll
            for (int k = 0; k < 4; k++) sc[g][k] = 0.f;

#pragma unroll
        for (int ks = 0; ks < 4; ks++) {
            const int rr = (l & 15);
            const int kc = ks * 16 + ((l >> 4) & 1) * 8;
#pragma unroll
            for (int kb = 0; kb < 4; kb++) {
                unsigned kh[4], kl[4];
                ldsm4(kh, smaddr(&Ks0[(kb * 16 + rr) * 72 + kc]));
                ldsm4(kl, smaddr(&Ks1[(kb * 16 + rr) * 72 + kc]));
                mma_bf16(sc[2 * kb],     qh[ks], kh[0], kh[2]);
                mma_bf16(sc[2 * kb],     qh[ks], kl[0], kl[2]);
                mma_bf16(sc[2 * kb],     ql[ks], kh[0], kh[2]);
                mma_bf16(sc[2 * kb + 1], qh[ks], kh[1], kh[3]);
                mma_bf16(sc[2 * kb + 1], qh[ks], kl[1], kl[3]);
                mma_bf16(sc[2 * kb + 1], ql[ks], kh[1], kh[3]);
            }
        }

        // online softmax (registers only; rows r=l/4, r+8)
        float mx0 = -1e30f, mx1 = -1e30f;
#pragma unroll
        for (int g = 0; g < 8; g++) {
            mx0 = fmaxf(mx0, fmaxf(sc[g][0], sc[g][1]));
            mx1 = fmaxf(mx1, fmaxf(sc[g][2], sc[g][3]));
        }
        mx0 = fmaxf(mx0, __shfl_xor_sync(0xffffffffu, mx0, 1));
        mx0 = fmaxf(mx0, __shfl_xor_sync(0xffffffffu, mx0, 2));
        mx1 = fmaxf(mx1, __shfl_xor_sync(0xffffffffu, mx1, 1));
        mx1 = fmaxf(mx1, __shfl_xor_sync(0xffffffffu, mx1, 2));
        const float mn0 = fmaxf(m0, mx0), mn1 = fmaxf(m1, mx1);
        const float al0 = __expf(m0 - mn0), al1 = __expf(m1 - mn1);
        m0 = mn0; m1 = mn1;
        float s0 = 0.f, s1 = 0.f;
#pragma unroll
        for (int g = 0; g < 8; g++) {
            sc[g][0] = __expf(sc[g][0] - mn0); s0 += sc[g][0];
            sc[g][1] = __expf(sc[g][1] - mn0); s0 += sc[g][1];
            sc[g][2] = __expf(sc[g][2] - mn1); s1 += sc[g][2];
            sc[g][3] = __expf(sc[g][3] - mn1); s1 += sc[g][3];
        }
        s0 += __shfl_xor_sync(0xffffffffu, s0, 1);
        s0 += __shfl_xor_sync(0xffffffffu, s0, 2);
        s1 += __shfl_xor_sync(0xffffffffu, s1, 1);
        s1 += __shfl_xor_sync(0xffffffffu, s1, 2);
        l0 = l0 * al0 + s0;
        l1 = l1 * al1 + s1;
#pragma unroll
        for (int g = 0; g < 8; g++) {
            o[g][0] *= al0; o[g][1] *= al0;
            o[g][2] *= al1; o[g][3] *= al1;
        }

        // PV: P (packed from sc) x V (trans B frags; V rows keys, hd contiguous)
#pragma unroll
        for (int j = 0; j < 4; j++) {
            unsigned ph[4], pl[4];
            split2(sc[2 * j][0],     sc[2 * j][1],     ph[0], pl[0]);
            split2(sc[2 * j][2],     sc[2 * j][3],     ph[1], pl[1]);
            split2(sc[2 * j + 1][0], sc[2 * j + 1][1], ph[2], pl[2]);
            split2(sc[2 * j + 1][2], sc[2 * j + 1][3], ph[3], pl[3]);
            const int rr2 = 16 * j + ((l >> 3) & 1) * 8 + (l & 7);
            const int cc2 = ((l >> 4) & 1) * 8;
#pragma unroll
            for (int nb = 0; nb < 4; nb++) {
                unsigned vh[4], vl[4];
                ldsm4t(vh, smaddr(&Vs0[rr2 * 72 + nb * 16 + cc2]));
                ldsm4t(vl, smaddr(&Vs1[rr2 * 72 + nb * 16 + cc2]));
                mma_bf16(o[2 * nb],     ph, vh[0], vh[1]);
                mma_bf16(o[2 * nb],     ph, vl[0], vl[1]);
                mma_bf16(o[2 * nb],     pl, vh[0], vh[1]);
                mma_bf16(o[2 * nb + 1], ph, vh[2], vh[3]);
                mma_bf16(o[2 * nb + 1], ph, vl[2], vl[3]);
                mma_bf16(o[2 * nb + 1], pl, vh[2], vh[3]);
            }
        }
        __syncthreads();
    }

    // epilogue: normalize, split to bf16 hi/lo, write g_a [4096,1024]
    const float inv0 = 1.f / l0, inv1 = 1.f / l1;
    const int r0 = qt * 64 + wid * 16 + (l >> 2);
    const int r1 = r0 + 8;
#pragma unroll
    for (int g = 0; g < 8; g++) {
        const int col = h * 64 + g * 8 + 2 * (l & 3);
        unsigned hp, lp;
        split2(o[g][0] * inv0, o[g][1] * inv0, hp, lp);
        *(unsigned*)&g_ah[(size_t)(b * S_ + r0) * D_ + col] = hp;
        *(unsigned*)&g_al[(size_t)(b * S_ + r0) * D_ + col] = lp;
        split2(o[g][2] * inv1, o[g][3] * inv1, hp, lp);
        *(unsigned*)&g_ah[(size_t)(b * S_ + r1) * D_ + col] = hp;
        *(unsigned*)&g_al[(size_t)(b * S_ + r1) * D_ + col] = lp;
    }
}

// ---------------------------------------------------------------------------
extern "C" void kernel_launch(void* const* d_in, const int* in_sizes, int n_in,
                              void* d_out, int out_size) {
    const float* x     = (const float*)d_in[0];
    const float* Wqkv  = (const float*)d_in[1];
    const float* bqkv  = (const float*)d_in[2];
    const float* Wproj = (const float*)d_in[3];
    const float* bproj = (const float*)d_in[4];
    float* out = (float*)d_out;

    conv_x    <<<NTOK * D_ / 1024, 256>>>(x);
    conv_wqkv <<<D_ * 3 * D_ / 1024, 256>>>(Wqkv);
    conv_wproj<<<D_ * D_ / 1024, 256>>>(Wproj);

    dim3 g1(3 * D_ / 128, NTOK / 128);              // 24 x 32
    gemm_split<3 * D_, 0><<<g1, 256>>>(bqkv, nullptr);

    dim3 g2(S_ / 64, H_, B_);                       // 32 x 16 x 2
    attn_mma<<<g2, 128>>>();

    dim3 g3(D_ / 128, NTOK / 128);                  // 8 x 32
    gemm_split<D_, 1><<<g3, 256>>>(bproj, out);
}

// round 4
// speedup vs baseline: 3.8273x; 1.0629x over previous
#include <cuda_runtime.h>
#include <cuda_bf16.h>

#define B_  2
#define S_  2048
#define D_  1024
#define H_  16
#define HD_ 64
#define SCALE_ 0.125f
#define NTOK (B_*S_)   /* 4096 */

// ---------------- device scratch (allocation-free rule) ----------------
__device__ __nv_bfloat16 g_xh[NTOK*D_],  g_xl[NTOK*D_];
__device__ __nv_bfloat16 g_wqh[D_*3*D_], g_wql[D_*3*D_];
__device__ __nv_bfloat16 g_wph[D_*D_],   g_wpl[D_*D_];
__device__ __nv_bfloat16 g_Qh[NTOK*D_],  g_Ql[NTOK*D_];   // [B,H,S,HD], Q pre-scaled
__device__ __nv_bfloat16 g_Kh[NTOK*D_],  g_Kl[NTOK*D_];
__device__ __nv_bfloat16 g_Vh[NTOK*D_],  g_Vl[NTOK*D_];
__device__ __nv_bfloat16 g_ah[NTOK*D_],  g_al[NTOK*D_];   // attention out [4096,1024]

// ---------------- helpers ----------------
__device__ __forceinline__ unsigned smaddr(const void* p) {
    return (unsigned)__cvta_generic_to_shared(p);
}
__device__ __forceinline__ void ldsm4(unsigned r[4], unsigned a) {
    asm volatile("ldmatrix.sync.aligned.m8n8.x4.shared.b16 {%0,%1,%2,%3}, [%4];"
                 : "=r"(r[0]), "=r"(r[1]), "=r"(r[2]), "=r"(r[3]) : "r"(a));
}
__device__ __forceinline__ void ldsm4t(unsigned r[4], unsigned a) {
    asm volatile("ldmatrix.sync.aligned.m8n8.x4.trans.shared.b16 {%0,%1,%2,%3}, [%4];"
                 : "=r"(r[0]), "=r"(r[1]), "=r"(r[2]), "=r"(r[3]) : "r"(a));
}
__device__ __forceinline__ void mma_bf16(float c[4], const unsigned a[4],
                                         unsigned b0, unsigned b1) {
    asm volatile(
        "mma.sync.aligned.m16n8k16.row.col.f32.bf16.bf16.f32 "
        "{%0,%1,%2,%3},{%4,%5,%6,%7},{%8,%9},{%0,%1,%2,%3};"
        : "+f"(c[0]), "+f"(c[1]), "+f"(c[2]), "+f"(c[3])
        : "r"(a[0]), "r"(a[1]), "r"(a[2]), "r"(a[3]), "r"(b0), "r"(b1));
}
// split two fp32 into packed-bf16 hi pair + lo pair
__device__ __forceinline__ void split2(float v0, float v1, unsigned& hp, unsigned& lp) {
    __nv_bfloat16 h0 = __float2bfloat16(v0), h1 = __float2bfloat16(v1);
    float r0 = v0 - __bfloat162float(h0), r1 = v1 - __bfloat162float(h1);
    __nv_bfloat162 hh = __halves2bfloat162(h0, h1);
    __nv_bfloat162 ll = __floats2bfloat162_rn(r0, r1);
    hp = *reinterpret_cast<unsigned*>(&hh);
    lp = *reinterpret_cast<unsigned*>(&ll);
}

// ---------------- fused split-convert (x, Wqkv, Wproj in one launch) --------
#define N_X4  (NTOK*D_/4)        /* 1048576 float4 */
#define N_WQ4 (D_*3*D_/4)        /*  786432 */
#define N_WP4 (D_*D_/4)          /*  262144 */
__global__ void conv_all(const float* __restrict__ x,
                         const float* __restrict__ wq,
                         const float* __restrict__ wp) {
    size_t i = (size_t)blockIdx.x * 256 + threadIdx.x;
    const float* src; __nv_bfloat16 *h, *l; size_t j;
    if (i < N_X4)                { src = x;  h = g_xh;  l = g_xl;  j = i; }
    else if (i < N_X4 + N_WQ4)   { src = wq; h = g_wqh; l = g_wql; j = i - N_X4; }
    else                         { src = wp; h = g_wph; l = g_wpl; j = i - N_X4 - N_WQ4; }
    float4 v = ((const float4*)src)[j];
    unsigned h0, l0, h1, l1;
    split2(v.x, v.y, h0, l0);
    split2(v.z, v.w, h1, l1);
    *(unsigned*)(h + j * 4)     = h0;  *(unsigned*)(h + j * 4 + 2) = h1;
    *(unsigned*)(l + j * 4)     = l0;  *(unsigned*)(l + j * 4 + 2) = l1;
}

// ---------------- split-bf16 GEMM (128x128 tile, BK=32, 8 warps) ----------------
// MODE 0: QKV  (A=g_x, B=g_wq; bias, Q*SCALE, scatter split-bf16 to g_Q/K/V)
// MODE 1: proj (A=g_a, B=g_wp; bias, fp32 out)
template <int GN, int MODE>
__global__ __launch_bounds__(256) void gemm_split(const float* __restrict__ bias,
                                                  float* __restrict__ outp) {
    const __nv_bfloat16* __restrict__ Ah = (MODE == 0) ? g_xh : g_ah;
    const __nv_bfloat16* __restrict__ Al = (MODE == 0) ? g_xl : g_al;
    const __nv_bfloat16* __restrict__ Bh = (MODE == 0) ? g_wqh : g_wph;
    const __nv_bfloat16* __restrict__ Bl = (MODE == 0) ? g_wql : g_wpl;

    __shared__ __nv_bfloat16 As0[128 * 40], As1[128 * 40];
    __shared__ __nv_bfloat16 Bs0[32 * 136], Bs1[32 * 136];

    const int tid = threadIdx.x, l = tid & 31, wid = tid >> 5;
    const int wm = (wid & 1) * 64, wn = (wid >> 1) * 32;
    const int rowBase = blockIdx.y * 128, colBase = blockIdx.x * 128;

    const int ar = tid >> 2,  ac = (tid & 3) * 8;
    const int br = tid >> 4,  bc = (tid & 15) * 8;

    const __nv_bfloat16* gA0 = Ah + (size_t)(rowBase + ar) * D_ + ac;
    const __nv_bfloat16* gA1 = Al + (size_t)(rowBase + ar) * D_ + ac;
    const __nv_bfloat16* gB0 = Bh + (size_t)br * GN + colBase + bc;
    const __nv_bfloat16* gB1 = Bl + (size_t)br * GN + colBase + bc;

    float c[4][4][4];
#pragma unroll
    for (int i = 0; i < 4; i++)
#pragma unroll
        for (int j = 0; j < 4; j++)
#pragma unroll
            for (int k = 0; k < 4; k++) c[i][j][k] = 0.f;

    *(uint4*)&As0[ar * 40 + ac]        = *(const uint4*)(gA0);
    *(uint4*)&As0[(ar + 64) * 40 + ac] = *(const uint4*)(gA0 + (size_t)64 * D_);
    *(uint4*)&As1[ar * 40 + ac]        = *(const uint4*)(gA1);
    *(uint4*)&As1[(ar + 64) * 40 + ac] = *(const uint4*)(gA1 + (size_t)64 * D_);
    *(uint4*)&Bs0[br * 136 + bc]       = *(const uint4*)(gB0);
    *(uint4*)&Bs0[(br + 16) * 136 + bc]= *(const uint4*)(gB0 + (size_t)16 * GN);
    *(uint4*)&Bs1[br * 136 + bc]       = *(const uint4*)(gB1);
    *(uint4*)&Bs1[(br + 16) * 136 + bc]= *(const uint4*)(gB1 + (size_t)16 * GN);
    __syncthreads();

    const int nK = D_ / 32;
    for (int kt = 0; kt < nK; kt++) {
        uint4 pa0a, pa0b, pa1a, pa1b, pb0a, pb0b, pb1a, pb1b;
        if (kt + 1 < nK) {
            const size_t aoff = (size_t)(kt + 1) * 32;
            pa0a = *(const uint4*)(gA0 + aoff);
            pa0b = *(const uint4*)(gA0 + aoff + (size_t)64 * D_);
            pa1a = *(const uint4*)(gA1 + aoff);
            pa1b = *(const uint4*)(gA1 + aoff + (size_t)64 * D_);
            const size_t boff = (size_t)(kt + 1) * 32 * GN;
            pb0a = *(const uint4*)(gB0 + boff);
            pb0b = *(const uint4*)(gB0 + boff + (size_t)16 * GN);
            pb1a = *(const uint4*)(gB1 + boff);
            pb1b = *(const uint4*)(gB1 + boff + (size_t)16 * GN);
        }

#pragma unroll
        for (int k0 = 0; k0 < 32; k0 += 16) {
            unsigned ah[4][4], al[4][4];
            const int arow = wm + (l & 15);
            const int akc  = k0 + ((l >> 4) & 1) * 8;
#pragma unroll
            for (int mi = 0; mi < 4; mi++) {
                ldsm4(ah[mi], smaddr(&As0[(arow + mi * 16) * 40 + akc]));
                ldsm4(al[mi], smaddr(&As1[(arow + mi * 16) * 40 + akc]));
            }
            const int brow = k0 + ((l >> 3) & 1) * 8 + (l & 7);
            const int bcol = wn + (l >> 4) * 8;
#pragma unroll
            for (int nj = 0; nj < 2; nj++) {
                unsigned bh[4], bl[4];
                ldsm4t(bh, smaddr(&Bs0[brow * 136 + bcol + nj * 16]));
                ldsm4t(bl, smaddr(&Bs1[brow * 136 + bcol + nj * 16]));
                // term-outer, tile-inner: dep distance 8 on each accumulator
#pragma unroll
                for (int mi = 0; mi < 4; mi++) mma_bf16(c[mi][2 * nj],     ah[mi], bh[0], bh[1]);
#pragma unroll
                for (int mi = 0; mi < 4; mi++) mma_bf16(c[mi][2 * nj + 1], ah[mi], bh[2], bh[3]);
#pragma unroll
                for (int mi = 0; mi < 4; mi++) mma_bf16(c[mi][2 * nj],     ah[mi], bl[0], bl[1]);
#pragma unroll
                for (int mi = 0; mi < 4; mi++) mma_bf16(c[mi][2 * nj + 1], ah[mi], bl[2], bl[3]);
#pragma unroll
                for (int mi = 0; mi < 4; mi++) mma_bf16(c[mi][2 * nj],     al[mi], bh[0], bh[1]);
#pragma unroll
                for (int mi = 0; mi < 4; mi++) mma_bf16(c[mi][2 * nj + 1], al[mi], bh[2], bh[3]);
            }
        }

        if (kt + 1 < nK) {
            __syncthreads();
            *(uint4*)&As0[ar * 40 + ac]         = pa0a;
            *(uint4*)&As0[(ar + 64) * 40 + ac]  = pa0b;
            *(uint4*)&As1[ar * 40 + ac]         = pa1a;
            *(uint4*)&As1[(ar + 64) * 40 + ac]  = pa1b;
            *(uint4*)&Bs0[br * 136 + bc]        = pb0a;
            *(uint4*)&Bs0[(br + 16) * 136 + bc] = pb0b;
            *(uint4*)&Bs1[br * 136 + bc]        = pb1a;
            *(uint4*)&Bs1[(br + 16) * 136 + bc] = pb1b;
            __syncthreads();
        }
    }

#pragma unroll
    for (int mi = 0; mi < 4; mi++) {
        const int r0 = rowBase + wm + mi * 16 + (l >> 2);
        const int r1 = r0 + 8;
#pragma unroll
        for (int g = 0; g < 4; g++) {
            const int nn = colBase + wn + g * 8 + 2 * (l & 3);
            if (MODE == 1) {
                float2 w;
                w.x = c[mi][g][0] + bias[nn];
                w.y = c[mi][g][1] + bias[nn + 1];
                *(float2*)(outp + (size_t)r0 * GN + nn) = w;
                w.x = c[mi][g][2] + bias[nn];
                w.y = c[mi][g][3] + bias[nn + 1];
                *(float2*)(outp + (size_t)r1 * GN + nn) = w;
            } else {
                const int which = nn >> 10, d = nn & 1023, hh = d >> 6, hd = d & 63;
                const float sc = (which == 0) ? SCALE_ : 1.f;
                __nv_bfloat16* dh = (which == 0) ? g_Qh : (which == 1) ? g_Kh : g_Vh;
                __nv_bfloat16* dl = (which == 0) ? g_Ql : (which == 1) ? g_Kl : g_Vl;
                const int b0i = r0 >> 11, s0i = r0 & 2047;
                const int b1i = r1 >> 11, s1i = r1 & 2047;
                const size_t i0 = (((size_t)(b0i * H_ + hh)) * S_ + s0i) * HD_ + hd;
                const size_t i1 = (((size_t)(b1i * H_ + hh)) * S_ + s1i) * HD_ + hd;
                unsigned hp, lp;
                split2((c[mi][g][0] + bias[nn]) * sc, (c[mi][g][1] + bias[nn + 1]) * sc, hp, lp);
                *(unsigned*)(dh + i0) = hp; *(unsigned*)(dl + i0) = lp;
                split2((c[mi][g][2] + bias[nn]) * sc, (c[mi][g][3] + bias[nn + 1]) * sc, hp, lp);
                *(unsigned*)(dh + i1) = hp; *(unsigned*)(dl + i1) = lp;
            }
        }
    }
}

// ---------------- flash attention, mma.sync split-bf16, interleaved issue ----
__global__ __launch_bounds__(128) void attn_mma() {
    const int qt = blockIdx.x, h = blockIdx.y, b = blockIdx.z;
    const int tid = threadIdx.x, l = tid & 31, wid = tid >> 5;

    __shared__ __nv_bfloat16 Ks0[64 * 72], Ks1[64 * 72];
    __shared__ __nv_bfloat16 Vs0[64 * 72], Vs1[64 * 72];

    const size_t headOff = ((size_t)(b * H_ + h)) * S_ * HD_;
    const __nv_bfloat16* Qh_g = g_Qh + headOff + (size_t)qt * 64 * HD_;
    const __nv_bfloat16* Ql_g = g_Ql + headOff + (size_t)qt * 64 * HD_;
    const __nv_bfloat16* Kh_g = g_Kh + headOff;
    const __nv_bfloat16* Kl_g = g_Kl + headOff;
    const __nv_bfloat16* Vh_g = g_Vh + headOff;
    const __nv_bfloat16* Vl_g = g_Vl + headOff;

    for (int i = tid; i < 64 * 8; i += 128) {
        const int r = i >> 3, cc = (i & 7) * 8;
        *(uint4*)&Ks0[r * 72 + cc] = *(const uint4*)(Qh_g + (size_t)r * HD_ + cc);
        *(uint4*)&Ks1[r * 72 + cc] = *(const uint4*)(Ql_g + (size_t)r * HD_ + cc);
    }
    __syncthreads();
    unsigned qh[4][4], ql[4][4];
    {
        const int row = wid * 16 + (l & 15);
        const int kc  = ((l >> 4) & 1) * 8;
#pragma unroll
        for (int ks = 0; ks < 4; ks++) {
            ldsm4(qh[ks], smaddr(&Ks0[row * 72 + ks * 16 + kc]));
            ldsm4(ql[ks], smaddr(&Ks1[row * 72 + ks * 16 + kc]));
        }
    }
    __syncthreads();

    float m0 = -1e30f, m1 = -1e30f, l0 = 0.f, l1 = 0.f;
    float o[8][4];
#pragma unroll
    for (int g = 0; g < 8; g++)
#pragma unroll
        for (int k = 0; k < 4; k++) o[g][k] = 0.f;

    for (int kt = 0; kt < S_ / 64; kt++) {
        const size_t koff = (size_t)kt * 64 * HD_;
        for (int i = tid; i < 64 * 8; i += 128) {
            const int r = i >> 3, cc = (i & 7) * 8;
            const size_t src = koff + (size_t)r * HD_ + cc;
            *(uint4*)&Ks0[r * 72 + cc] = *(const uint4*)(Kh_g + src);
            *(uint4*)&Ks1[r * 72 + cc] = *(const uint4*)(Kl_g + src);
            *(uint4*)&Vs0[r * 72 + cc] = *(const uint4*)(Vh_g + src);
            *(uint4*)&Vs1[r * 72 + cc] = *(const uint4*)(Vl_g + src);
        }
        __syncthreads();

        float sc[8][4];
#pragma unroll
        for (int g = 0; g < 8; g++)
#pragma unroll
            for (int k = 0; k < 4; k++) sc[g][k] = 0.f;

        const int rr = (l & 15);
#pragma unroll
        for (int ks = 0; ks < 4; ks++) {
            const int kc = ks * 16 + ((l >> 4) & 1) * 8;
            unsigned kh[4][4], kl[4][4];
#pragma unroll
            for (int kb = 0; kb < 4; kb++) {
                ldsm4(kh[kb], smaddr(&Ks0[(kb * 16 + rr) * 72 + kc]));
                ldsm4(kl[kb], smaddr(&Ks1[(kb * 16 + rr) * 72 + kc]));
            }
            // interleaved: dep distance 8
#pragma unroll
            for (int kb = 0; kb < 4; kb++) {
                mma_bf16(sc[2 * kb],     qh[ks], kh[kb][0], kh[kb][2]);
                mma_bf16(sc[2 * kb + 1], qh[ks], kh[kb][1], kh[kb][3]);
            }
#pragma unroll
            for (int kb = 0; kb < 4; kb++) {
                mma_bf16(sc[2 * kb],     qh[ks], kl[kb][0], kl[kb][2]);
                mma_bf16(sc[2 * kb + 1], qh[ks], kl[kb][1], kl[kb][3]);
            }
#pragma unroll
            for (int kb = 0; kb < 4; kb++) {
                mma_bf16(sc[2 * kb],     ql[ks], kh[kb][0], kh[kb][2]);
                mma_bf16(sc[2 * kb + 1], ql[ks], kh[kb][1], kh[kb][3]);
            }
        }

        // online softmax (registers only; rows r=l/4, r+8)
        float mx0 = -1e30f, mx1 = -1e30f;
#pragma unroll
        for (int g = 0; g < 8; g++) {
            mx0 = fmaxf(mx0, fmaxf(sc[g][0], sc[g][1]));
            mx1 = fmaxf(mx1, fmaxf(sc[g][2], sc[g][3]));
        }
        mx0 = fmaxf(mx0, __shfl_xor_sync(0xffffffffu, mx0, 1));
        mx0 = fmaxf(mx0, __shfl_xor_sync(0xffffffffu, mx0, 2));
        mx1 = fmaxf(mx1, __shfl_xor_sync(0xffffffffu, mx1, 1));
        mx1 = fmaxf(mx1, __shfl_xor_sync(0xffffffffu, mx1, 2));
        const float mn0 = fmaxf(m0, mx0), mn1 = fmaxf(m1, mx1);
        const float al0 = __expf(m0 - mn0), al1 = __expf(m1 - mn1);
        m0 = mn0; m1 = mn1;
        float s0 = 0.f, s1 = 0.f;
#pragma unroll
        for (int g = 0; g < 8; g++) {
            sc[g][0] = __expf(sc[g][0] - mn0); s0 += sc[g][0];
            sc[g][1] = __expf(sc[g][1] - mn0); s0 += sc[g][1];
            sc[g][2] = __expf(sc[g][2] - mn1); s1 += sc[g][2];
            sc[g][3] = __expf(sc[g][3] - mn1); s1 += sc[g][3];
        }
        s0 += __shfl_xor_sync(0xffffffffu, s0, 1);
        s0 += __shfl_xor_sync(0xffffffffu, s0, 2);
        s1 += __shfl_xor_sync(0xffffffffu, s1, 1);
        s1 += __shfl_xor_sync(0xffffffffu, s1, 2);
        l0 = l0 * al0 + s0;
        l1 = l1 * al1 + s1;
#pragma unroll
        for (int g = 0; g < 8; g++) {
            o[g][0] *= al0; o[g][1] *= al0;
            o[g][2] *= al1; o[g][3] *= al1;
        }

        // PV: per 16-key slab, preload all V frags, interleaved issue
#pragma unroll
        for (int j = 0; j < 4; j++) {
            unsigned ph[4], pl[4];
            split2(sc[2 * j][0],     sc[2 * j][1],     ph[0], pl[0]);
            split2(sc[2 * j][2],     sc[2 * j][3],     ph[1], pl[1]);
            split2(sc[2 * j + 1][0], sc[2 * j + 1][1], ph[2], pl[2]);
            split2(sc[2 * j + 1][2], sc[2 * j + 1][3], ph[3], pl[3]);
            const int rr2 = 16 * j + ((l >> 3) & 1) * 8 + (l & 7);
            const int cc2 = ((l >> 4) & 1) * 8;
            unsigned vh[4][4], vl[4][4];
#pragma unroll
            for (int nb = 0; nb < 4; nb++) {
                ldsm4t(vh[nb], smaddr(&Vs0[rr2 * 72 + nb * 16 + cc2]));
                ldsm4t(vl[nb], smaddr(&Vs1[rr2 * 72 + nb * 16 + cc2]));
            }
#pragma unroll
            for (int nb = 0; nb < 4; nb++) {
                mma_bf16(o[2 * nb],     ph, vh[nb][0], vh[nb][1]);
                mma_bf16(o[2 * nb + 1], ph, vh[nb][2], vh[nb][3]);
            }
#pragma unroll
            for (int nb = 0; nb < 4; nb++) {
                mma_bf16(o[2 * nb],     ph, vl[nb][0], vl[nb][1]);
                mma_bf16(o[2 * nb + 1], ph, vl[nb][2], vl[nb][3]);
            }
#pragma unroll
            for (int nb = 0; nb < 4; nb++) {
                mma_bf16(o[2 * nb],     pl, vh[nb][0], vh[nb][1]);
                mma_bf16(o[2 * nb + 1], pl, vh[nb][2], vh[nb][3]);
            }
        }
        __syncthreads();
    }

    const float inv0 = 1.f / l0, inv1 = 1.f / l1;
    const int r0 = qt * 64 + wid * 16 + (l >> 2);
    const int r1 = r0 + 8;
#pragma unroll
    for (int g = 0; g < 8; g++) {
        const int col = h * 64 + g * 8 + 2 * (l & 3);
        unsigned hp, lp;
        split2(o[g][0] * inv0, o[g][1] * inv0, hp, lp);
        *(unsigned*)&g_ah[(size_t)(b * S_ + r0) * D_ + col] = hp;
        *(unsigned*)&g_al[(size_t)(b * S_ + r0) * D_ + col] = lp;
        split2(o[g][2] * inv1, o[g][3] * inv1, hp, lp);
        *(unsigned*)&g_ah[(size_t)(b * S_ + r1) * D_ + col] = hp;
        *(unsigned*)&g_al[(size_t)(b * S_ + r1) * D_ + col] = lp;
    }
}

// ---------------------------------------------------------------------------
extern "C" void kernel_launch(void* const* d_in, const int* in_sizes, int n_in,
                              void* d_out, int out_size) {
    const float* x     = (const float*)d_in[0];
    const float* Wqkv  = (const float*)d_in[1];
    const float* bqkv  = (const float*)d_in[2];
    const float* Wproj = (const float*)d_in[3];
    const float* bproj = (const float*)d_in[4];
    float* out = (float*)d_out;

    conv_all<<<(N_X4 + N_WQ4 + N_WP4) / 256, 256>>>(x, Wqkv, Wproj);

    dim3 g1(3 * D_ / 128, NTOK / 128);              // 24 x 32
    gemm_split<3 * D_, 0><<<g1, 256>>>(bqkv, nullptr);

    dim3 g2(S_ / 64, H_, B_);                       // 32 x 16 x 2
    attn_mma<<<g2, 128>>>();

    dim3 g3(D_ / 128, NTOK / 128);                  // 8 x 32
    gemm_split<D_, 1><<<g3, 256>>>(bproj, out);
}